// round 12
// baseline (speedup 1.0000x reference)
#include <cuda_runtime.h>
#include <math.h>

// Problem constants: N=8, S=8192, C=1, K=1024, V=64
#define NS_TOTAL 65536
#define VDIM 64
#define KCW 1024
#define BM 64                  // rows per CTA
#define BK 256
#define NCHUNK (KCW / BK)      // 4
#define GRID 1024
#define THREADS 256

#define XST 132                // x stride: 2*BM + 4 (16B-aligned rows for LDS.128)
#define EST 258                // e stride: BK + 2
#define XS_FLOATS (VDIM * XST) // 8448
#define ES_FLOATS (VDIM * EST) // 16512
#define SMEM_BYTES ((XS_FLOATS + ES_FLOATS + KCW + BM) * 4)   // 104192 -> 2 CTAs/SM

typedef unsigned long long ull;

__device__ float g_en[KCW];
__device__ int   g_counts[KCW];   // zero at load; last CTA re-zeroes each run
__device__ int   g_done;          // zero at load; last CTA resets each run

// Packed fp32x2 ops — IEEE rn per 32-bit lane (native FFMA2 on this part).
__device__ __forceinline__ ull ffma2(ull a, ull b, ull c) {
    ull d;
    asm("fma.rn.f32x2 %0, %1, %2, %3;" : "=l"(d) : "l"(a), "l"(b), "l"(c));
    return d;
}
__device__ __forceinline__ ull fmul2(ull a, ull b) {
    ull d;
    asm("mul.rn.f32x2 %0, %1, %2;" : "=l"(d) : "l"(a), "l"(b));
    return d;
}
__device__ __forceinline__ ull fadd2(ull a, ull b) {
    ull d;
    asm("add.rn.f32x2 %0, %1, %2;" : "=l"(d) : "l"(a), "l"(b));
    return d;
}
__device__ __forceinline__ void unpack2(ull v, float& lo, float& hi) {
    unsigned int l, h;
    asm("mov.b64 {%0, %1}, %2;" : "=r"(l), "=r"(h) : "l"(v));
    lo = __uint_as_float(l);
    hi = __uint_as_float(h);
}
__device__ __forceinline__ ull pack2(float lo, float hi) {
    ull v;
    asm("mov.b64 %0, {%1, %2};" : "=l"(v) : "f"(lo), "f"(hi));
    return v;
}

// e-tile bank swizzle: float-index idx -> idx ^ (4*((v>>2)&7)).
#define ESWZ(v) (4 * (((v) >> 2) & 7))

// ---------------------------------------------------------------------------
// Kernel 1: codeword norms via coalesced smem staging (bit-exact sequential).
// ---------------------------------------------------------------------------
__global__ void vq_prep_kernel(const float* __restrict__ emb) {
    __shared__ float se[64 * 65];
    const int tid = threadIdx.x;
    const int kb  = blockIdx.x * 64;
    const float4* e4 = reinterpret_cast<const float4*>(emb) + (size_t)kb * (VDIM / 4);
    #pragma unroll
    for (int t = 0; t < 4; t++) {
        int idx = tid + t * 256;           // 1024 float4
        int r   = idx >> 4;
        int v4  = idx & 15;
        float4 f = e4[idx];
        float* d = se + r * 65 + v4 * 4;
        d[0] = f.x; d[1] = f.y; d[2] = f.z; d[3] = f.w;
    }
    __syncthreads();
    if (tid < 64) {
        const float* er = se + tid * 65;
        float acc = 0.0f;
        #pragma unroll 8
        for (int v = 0; v < VDIM; v++)
            acc = __fadd_rn(acc, __fmul_rn(er[v], er[v]));
        g_en[kb + tid] = acc;
    }
}

// ---------------------------------------------------------------------------
// Kernel 2: fused GEMM + argmin + histogram + outputs + (last CTA) entropy
// grid 1024 (64 samples each), 256 threads, 2 CTAs/SM (128-reg cap)
// thread tile: 8 contiguous rows (warp-owned) x 8 codewords (4 packed pairs)
// ---------------------------------------------------------------------------
__global__ __launch_bounds__(THREADS, 2)
void vq_main_kernel(const float* __restrict__ x, const float* __restrict__ emb,
                    float* __restrict__ out0, float* __restrict__ out1,
                    float* __restrict__ out2, float* __restrict__ ent) {
    extern __shared__ float sm[];
    float* xs2  = sm;                          // [VDIM][XST] duplicated x pairs
    float* es   = sm + XS_FLOATS;              // [VDIM][EST] e chunk (transposed, swizzled)
    float* en_s = sm + XS_FLOATS + ES_FLOATS;  // [KCW] codeword norms
    float* xn_s = en_s + KCW;                  // [BM] row norms
    // post-loop overlays on es:
    int*   amin_s  = (int*)es;                 // [BM]
    float* rowsum  = es + BM;                  // [BM]

    const int tid  = threadIdx.x;
    const int lane = tid & 31;                 // 32 codeword-pair groups
    const int wrp  = tid >> 5;                 // 8 warps: rows 8*wrp .. 8*wrp+7
    const int row0 = blockIdx.x * BM;

    // ---- load x tile (coalesced float4), store duplicated pairs (v-major) ----
    const float4* x4 = reinterpret_cast<const float4*>(x) + (size_t)row0 * (VDIM / 4);
    #pragma unroll
    for (int t = 0; t < 4; t++) {
        int lin4 = tid + t * THREADS;          // 1024 float4
        int r    = lin4 >> 4;
        int v4   = lin4 & 15;
        float4 val = x4[lin4];
        *reinterpret_cast<float2*>(xs2 + (v4 * 4 + 0) * XST + 2 * r) = make_float2(val.x, val.x);
        *reinterpret_cast<float2*>(xs2 + (v4 * 4 + 1) * XST + 2 * r) = make_float2(val.y, val.y);
        *reinterpret_cast<float2*>(xs2 + (v4 * 4 + 2) * XST + 2 * r) = make_float2(val.z, val.z);
        *reinterpret_cast<float2*>(xs2 + (v4 * 4 + 3) * XST + 2 * r) = make_float2(val.w, val.w);
    }
    // ---- copy codeword norms into smem (4 per thread) ----
    #pragma unroll
    for (int t = 0; t < 4; t++) en_s[tid + t * THREADS] = g_en[tid + t * THREADS];
    __syncthreads();

    // ---- row norms ||x_r||^2 (sequential mul+add, v ascending) ----
    if (tid < BM) {
        float acc = 0.0f;
        const float* xr = xs2 + 2 * tid;
        #pragma unroll 8
        for (int v = 0; v < VDIM; v++) {
            float xv = xr[v * XST];
            acc = __fadd_rn(acc, __fmul_rn(xv, xv));
        }
        xn_s[tid] = acc;
    }

    float minv[8];
    int   mini[8];
    #pragma unroll
    for (int i = 0; i < 8; i++) { minv[i] = 3.402823466e38f; mini[i] = 0; }

    const ull NEG2 = 0xC0000000C0000000ULL;    // {-2.0f, -2.0f}

    // thread covers rows r_i = 8*wrp + i (i<8), codewords k = c*256 + 64*m + 2*lane + {0,1} (m<4)
    for (int c = 0; c < NCHUNK; c++) {
        if (c > 0) __syncthreads();            // compute done before overwriting es
        const float4* e4 = reinterpret_cast<const float4*>(emb) + (size_t)c * (BK * VDIM / 4);
        #pragma unroll
        for (int t = 0; t < 16; t++) {
            int lin4 = tid + t * THREADS;      // 4096 float4
            int k    = lin4 >> 4;
            int v4   = lin4 & 15;
            float4 val = e4[lin4];
            int swz = 4 * (v4 & 7);            // ESWZ(4*v4+j) == ESWZ(4*v4)
            es[(((v4 * 4 + 0) * EST + k)) ^ swz] = val.x;
            es[(((v4 * 4 + 1) * EST + k)) ^ swz] = val.y;
            es[(((v4 * 4 + 2) * EST + k)) ^ swz] = val.z;
            es[(((v4 * 4 + 3) * EST + k)) ^ swz] = val.w;
        }
        __syncthreads();

        ull acc[8][4];
        #pragma unroll
        for (int i = 0; i < 8; i++)
            #pragma unroll
            for (int m = 0; m < 4; m++) acc[i][m] = 0ULL;

        const int txk = 2 * lane;
        // sequential FMA over v=0..63, single accumulator per (row, codeword)
        #pragma unroll 8
        for (int v = 0; v < VDIM; v++) {
            int ei = (v * EST + txk) ^ ESWZ(v);
            ull ep[4];
            #pragma unroll
            for (int m = 0; m < 4; m++)
                ep[m] = *reinterpret_cast<const ull*>(es + ei + 64 * m);
            // x: 8 contiguous duplicated pairs, warp-uniform -> 4 broadcast LDS.128
            ull xp[8];
            const ulonglong2* xvp =
                reinterpret_cast<const ulonglong2*>(xs2 + v * XST + wrp * 16);
            #pragma unroll
            for (int j = 0; j < 4; j++) {
                ulonglong2 q = xvp[j];
                xp[2 * j]     = q.x;
                xp[2 * j + 1] = q.y;
            }
            #pragma unroll
            for (int i = 0; i < 8; i++)
                #pragma unroll
                for (int m = 0; m < 4; m++)
                    acc[i][m] = ffma2(xp[i], ep[m], acc[i][m]);
        }

        // score = fl( fl( xn - fl(2*dot) ) + en ) via packed ops (exact per lane)
        ull xn2[8];
        #pragma unroll
        for (int i = 0; i < 8; i++) {
            float xnv = xn_s[8 * wrp + i];
            xn2[i] = pack2(xnv, xnv);
        }
        #pragma unroll
        for (int m = 0; m < 4; m++) {
            int k0 = c * BK + 64 * m + txk;    // global codeword pair base
            ull en2 = *reinterpret_cast<const ull*>(en_s + k0);
            #pragma unroll
            for (int i = 0; i < 8; i++) {
                ull s2 = fadd2(fadd2(xn2[i], fmul2(acc[i][m], NEG2)), en2);
                float s0, s1;
                unpack2(s2, s0, s1);
                if (s0 < minv[i]) { minv[i] = s0; mini[i] = k0; }
                if (s1 < minv[i]) { minv[i] = s1; mini[i] = k0 + 1; }
            }
        }
    }

    // ---- warp-local argmin reduction (32 candidates per row, all in-warp) ----
    #pragma unroll
    for (int i = 0; i < 8; i++) {
        float bv = minv[i];
        int   bi = mini[i];
        #pragma unroll
        for (int off = 16; off > 0; off >>= 1) {
            float ov = __shfl_down_sync(0xffffffffu, bv, off);
            int   oi = __shfl_down_sync(0xffffffffu, bi, off);
            if (ov < bv || (ov == bv && oi < bi)) { bv = ov; bi = oi; }
        }
        minv[i] = bv;
        mini[i] = bi;
    }
    __syncthreads();                           // all es reads done before overlay writes
    if (lane == 0) {
        #pragma unroll
        for (int i = 0; i < 8; i++) {
            int r = 8 * wrp + i;
            amin_s[r] = mini[i];
            rowsum[r] = 0.0f;
            atomicAdd(&g_counts[mini[i]], 1);
        }
    }
    __syncthreads();

    // ---- outputs: out0 = fl(fl(o - x) + x), out1 = out2 = sum_v (x-o)^2 ----
    #pragma unroll 4
    for (int t = 0; t < 16; t++) {
        int i = t * THREADS + tid;             // 4096 elements; warp = half a row
        int r = i >> 6;
        int v = i & 63;
        float o  = emb[amin_s[r] * VDIM + v];
        float xv = xs2[v * XST + 2 * r];
        float d  = __fsub_rn(xv, o);
        float sq = __fmul_rn(d, d);
        #pragma unroll
        for (int off = 16; off > 0; off >>= 1)
            sq += __shfl_down_sync(0xffffffffu, sq, off);
        if (lane == 0) atomicAdd(&rowsum[r], sq);   // 2 adds/row: order-invariant
        out0[(size_t)(row0 + r) * VDIM + v] = __fadd_rn(__fsub_rn(o, xv), xv);
    }
    __syncthreads();
    if (tid < BM) {
        float s = rowsum[tid];
        out1[row0 + tid] = s;
        out2[row0 + tid] = s;
    }

    // ---- last CTA computes entropy and resets state for the next replay ----
    __threadfence();                           // order this CTA's atomics/stores
    __shared__ int is_last;
    __syncthreads();
    if (tid == 0) {
        int d = atomicAdd(&g_done, 1);
        is_last = (d == GRID - 1);
    }
    __syncthreads();
    if (is_last) {
        // 256 threads x 4 bins each
        float term = 0.0f;
        #pragma unroll
        for (int t = 0; t < 4; t++) {
            int k = tid + t * THREADS;
            int c = g_counts[k];
            g_counts[k] = 0;
            if (c > 0) {
                float p = (float)c * (1.0f / 65536.0f);
                term -= p * logf(p);
            }
        }
        #pragma unroll
        for (int off = 16; off > 0; off >>= 1)
            term += __shfl_down_sync(0xffffffffu, term, off);
        float* wsum = rowsum;                  // reuse smem
        if (lane == 0) wsum[wrp] = term;
        __syncthreads();
        if (tid == 0) {
            float s = 0.0f;
            #pragma unroll
            for (int wI = 0; wI < 8; wI++) s += wsum[wI];
            *ent = s;
            g_done = 0;
        }
    }
}

// ---------------------------------------------------------------------------
extern "C" void kernel_launch(void* const* d_in, const int* in_sizes, int n_in,
                              void* d_out, int out_size) {
    const float* x;
    const float* emb;
    if (in_sizes[0] == NS_TOTAL * VDIM) {
        x   = (const float*)d_in[0];
        emb = (const float*)d_in[1];
    } else {
        x   = (const float*)d_in[1];
        emb = (const float*)d_in[0];
    }

    float* out0 = (float*)d_out;                        // 65536*64
    float* out1 = out0 + (size_t)NS_TOTAL * VDIM;       // 65536
    float* out2 = out1 + NS_TOTAL;                      // 65536
    float* ent  = out2 + NS_TOTAL;                      // 1

    cudaFuncSetAttribute(vq_main_kernel,
                         cudaFuncAttributeMaxDynamicSharedMemorySize, SMEM_BYTES);

    vq_prep_kernel<<<16, 256>>>(emb);
    vq_main_kernel<<<GRID, THREADS, SMEM_BYTES>>>(x, emb, out0, out1, out2, ent);
}

// round 13
// speedup vs baseline: 1.3445x; 1.3445x over previous
#include <cuda_runtime.h>
#include <math.h>

// Problem constants: N=8, S=8192, C=1, K=1024, V=64
#define NS_TOTAL 65536
#define VDIM 64
#define KCW 1024
#define BM 32                  // rows per CTA
#define BK 128
#define NCHUNK (KCW / BK)      // 8
#define GRID 2048
#define THREADS 128

#define XST 68                 // x stride: 2*BM + 4 (16B-aligned rows)
#define EST 130                // e stride: BK + 2
#define XS_FLOATS (VDIM * XST) // 4352
#define ES_FLOATS (VDIM * EST) // 8320
// actual use: (4352+8320+1024+32)*4 = 54912 B; pad to pin exactly 3 CTAs/SM
#define SMEM_BYTES 72000

typedef unsigned long long ull;

__device__ float g_en[KCW];
__device__ int   g_counts[KCW];   // zero at load; last CTA re-zeroes each run
__device__ int   g_done;          // zero at load; last CTA resets each run

// Packed fp32x2 ops — IEEE rn per 32-bit lane (native FFMA2; must keep regs
// below the cap or ptxas splits them to scalar FFMA, R12 lesson).
__device__ __forceinline__ ull ffma2(ull a, ull b, ull c) {
    ull d;
    asm("fma.rn.f32x2 %0, %1, %2, %3;" : "=l"(d) : "l"(a), "l"(b), "l"(c));
    return d;
}
__device__ __forceinline__ ull fmul2(ull a, ull b) {
    ull d;
    asm("mul.rn.f32x2 %0, %1, %2;" : "=l"(d) : "l"(a), "l"(b));
    return d;
}
__device__ __forceinline__ ull fadd2(ull a, ull b) {
    ull d;
    asm("add.rn.f32x2 %0, %1, %2;" : "=l"(d) : "l"(a), "l"(b));
    return d;
}
__device__ __forceinline__ void unpack2(ull v, float& lo, float& hi) {
    unsigned int l, h;
    asm("mov.b64 {%0, %1}, %2;" : "=r"(l), "=r"(h) : "l"(v));
    lo = __uint_as_float(l);
    hi = __uint_as_float(h);
}
__device__ __forceinline__ ull pack2(float lo, float hi) {
    ull v;
    asm("mov.b64 %0, {%1, %2};" : "=l"(v) : "f"(lo), "f"(hi));
    return v;
}

// e-tile bank swizzle: float-index idx -> idx ^ (4*((v>>2)&7)).
#define ESWZ(v) (4 * (((v) >> 2) & 7))

// ---------------------------------------------------------------------------
// Kernel 1: codeword norms via coalesced smem staging (bit-exact sequential).
// ---------------------------------------------------------------------------
__global__ void vq_prep_kernel(const float* __restrict__ emb) {
    __shared__ float se[64 * 65];
    const int tid = threadIdx.x;
    const int kb  = blockIdx.x * 64;
    const float4* e4 = reinterpret_cast<const float4*>(emb) + (size_t)kb * (VDIM / 4);
    #pragma unroll
    for (int t = 0; t < 4; t++) {
        int idx = tid + t * 256;           // 1024 float4
        int r   = idx >> 4;
        int v4  = idx & 15;
        float4 f = e4[idx];
        float* d = se + r * 65 + v4 * 4;
        d[0] = f.x; d[1] = f.y; d[2] = f.z; d[3] = f.w;
    }
    __syncthreads();
    if (tid < 64) {
        const float* er = se + tid * 65;
        float acc = 0.0f;
        #pragma unroll 8
        for (int v = 0; v < VDIM; v++)
            acc = __fadd_rn(acc, __fmul_rn(er[v], er[v]));
        g_en[kb + tid] = acc;
    }
}

// ---------------------------------------------------------------------------
// Kernel 2: fused GEMM + argmin + histogram + outputs + (last CTA) entropy
// grid 2048 (32 samples each), 128 threads, 3 CTAs/SM (168-reg cap, ~100 used)
// thread tile: 8 contiguous rows (warp-owned) x 4 codewords (2 packed pairs)
// ---------------------------------------------------------------------------
__global__ __launch_bounds__(THREADS, 3)
void vq_main_kernel(const float* __restrict__ x, const float* __restrict__ emb,
                    float* __restrict__ out0, float* __restrict__ out1,
                    float* __restrict__ out2, float* __restrict__ ent) {
    extern __shared__ float sm[];
    float* xs2  = sm;                          // [VDIM][XST] duplicated x pairs
    float* es   = sm + XS_FLOATS;              // [VDIM][EST] e chunk (transposed, swizzled)
    float* en_s = sm + XS_FLOATS + ES_FLOATS;  // [KCW] codeword norms
    float* xn_s = en_s + KCW;                  // [BM] row norms
    // post-loop overlays on es:
    int*   amin_s  = (int*)es;                 // [BM]
    float* rowsum  = es + BM;                  // [BM]

    const int tid  = threadIdx.x;
    const int lane = tid & 31;                 // 32 codeword-pair groups
    const int wrp  = tid >> 5;                 // 4 warps: rows 8*wrp .. 8*wrp+7
    const int row0 = blockIdx.x * BM;

    // ---- load x tile (coalesced float4), store duplicated pairs (v-major) ----
    const float4* x4 = reinterpret_cast<const float4*>(x) + (size_t)row0 * (VDIM / 4);
    #pragma unroll
    for (int t = 0; t < 4; t++) {
        int lin4 = tid + t * THREADS;          // 512 float4
        int r    = lin4 >> 4;
        int v4   = lin4 & 15;
        float4 val = x4[lin4];
        *reinterpret_cast<float2*>(xs2 + (v4 * 4 + 0) * XST + 2 * r) = make_float2(val.x, val.x);
        *reinterpret_cast<float2*>(xs2 + (v4 * 4 + 1) * XST + 2 * r) = make_float2(val.y, val.y);
        *reinterpret_cast<float2*>(xs2 + (v4 * 4 + 2) * XST + 2 * r) = make_float2(val.z, val.z);
        *reinterpret_cast<float2*>(xs2 + (v4 * 4 + 3) * XST + 2 * r) = make_float2(val.w, val.w);
    }
    // ---- copy codeword norms into smem (8 per thread) ----
    #pragma unroll
    for (int t = 0; t < 8; t++) en_s[tid + t * THREADS] = g_en[tid + t * THREADS];
    __syncthreads();

    // ---- row norms ||x_r||^2 (sequential mul+add, v ascending) ----
    if (tid < BM) {
        float acc = 0.0f;
        const float* xr = xs2 + 2 * tid;
        #pragma unroll 8
        for (int v = 0; v < VDIM; v++) {
            float xv = xr[v * XST];
            acc = __fadd_rn(acc, __fmul_rn(xv, xv));
        }
        xn_s[tid] = acc;
    }

    float minv[8];
    int   mini[8];
    #pragma unroll
    for (int i = 0; i < 8; i++) { minv[i] = 3.402823466e38f; mini[i] = 0; }

    const ull NEG2 = 0xC0000000C0000000ULL;    // {-2.0f, -2.0f}

    // thread covers rows r_i = 8*wrp + i (i<8), codewords k = c*128 + 64*m + 2*lane + {0,1} (m<2)
    for (int c = 0; c < NCHUNK; c++) {
        if (c > 0) __syncthreads();            // compute done before overwriting es
        const float4* e4 = reinterpret_cast<const float4*>(emb) + (size_t)c * (BK * VDIM / 4);
        #pragma unroll
        for (int t = 0; t < 16; t++) {
            int lin4 = tid + t * THREADS;      // 2048 float4
            int k    = lin4 >> 4;
            int v4   = lin4 & 15;
            float4 val = e4[lin4];
            int swz = 4 * (v4 & 7);            // ESWZ(4*v4+j) == ESWZ(4*v4)
            es[(((v4 * 4 + 0) * EST + k)) ^ swz] = val.x;
            es[(((v4 * 4 + 1) * EST + k)) ^ swz] = val.y;
            es[(((v4 * 4 + 2) * EST + k)) ^ swz] = val.z;
            es[(((v4 * 4 + 3) * EST + k)) ^ swz] = val.w;
        }
        __syncthreads();

        ull acc[8][2];
        #pragma unroll
        for (int i = 0; i < 8; i++) {
            acc[i][0] = 0ULL;
            acc[i][1] = 0ULL;
        }

        const int txk = 2 * lane;
        // sequential FMA over v=0..63, single accumulator per (row, codeword)
        #pragma unroll 8
        for (int v = 0; v < VDIM; v++) {
            int ei = (v * EST + txk) ^ ESWZ(v);
            ull ep0 = *reinterpret_cast<const ull*>(es + ei);
            ull ep1 = *reinterpret_cast<const ull*>(es + ei + 64);
            // x: 8 contiguous duplicated pairs, warp-uniform -> 4 broadcast LDS.128
            ull xp[8];
            const ulonglong2* xvp =
                reinterpret_cast<const ulonglong2*>(xs2 + v * XST + wrp * 16);
            #pragma unroll
            for (int j = 0; j < 4; j++) {
                ulonglong2 q = xvp[j];
                xp[2 * j]     = q.x;
                xp[2 * j + 1] = q.y;
            }
            #pragma unroll
            for (int i = 0; i < 8; i++) {
                acc[i][0] = ffma2(xp[i], ep0, acc[i][0]);
                acc[i][1] = ffma2(xp[i], ep1, acc[i][1]);
            }
        }

        // score = fl( fl( xn - fl(2*dot) ) + en ) via packed ops (exact per lane)
        #pragma unroll
        for (int m = 0; m < 2; m++) {
            int k0 = c * BK + 64 * m + txk;    // global codeword pair base
            ull en2 = *reinterpret_cast<const ull*>(en_s + k0);
            #pragma unroll
            for (int i = 0; i < 8; i++) {
                float xnv = xn_s[8 * wrp + i];
                ull s2 = fadd2(fadd2(pack2(xnv, xnv), fmul2(acc[i][m], NEG2)), en2);
                float s0, s1;
                unpack2(s2, s0, s1);
                if (s0 < minv[i]) { minv[i] = s0; mini[i] = k0; }
                if (s1 < minv[i]) { minv[i] = s1; mini[i] = k0 + 1; }
            }
        }
    }

    // ---- warp-local argmin reduction (all candidates for a row are in-warp) ----
    #pragma unroll
    for (int i = 0; i < 8; i++) {
        float bv = minv[i];
        int   bi = mini[i];
        #pragma unroll
        for (int off = 16; off > 0; off >>= 1) {
            float ov = __shfl_down_sync(0xffffffffu, bv, off);
            int   oi = __shfl_down_sync(0xffffffffu, bi, off);
            if (ov < bv || (ov == bv && oi < bi)) { bv = ov; bi = oi; }
        }
        mini[i] = bi;
    }
    __syncthreads();                           // all es reads done before overlay writes
    if (lane == 0) {
        #pragma unroll
        for (int i = 0; i < 8; i++) {
            int r = 8 * wrp + i;
            amin_s[r] = mini[i];
            rowsum[r] = 0.0f;
            atomicAdd(&g_counts[mini[i]], 1);
        }
    }
    __syncthreads();

    // ---- outputs: out0 = fl(fl(o - x) + x), out1 = out2 = sum_v (x-o)^2 ----
    #pragma unroll 4
    for (int t = 0; t < 16; t++) {
        int i = t * THREADS + tid;             // 2048 elements; warp = half a row
        int r = i >> 6;
        int v = i & 63;
        float o  = emb[amin_s[r] * VDIM + v];
        float xv = xs2[v * XST + 2 * r];
        float d  = __fsub_rn(xv, o);
        float sq = __fmul_rn(d, d);
        #pragma unroll
        for (int off = 16; off > 0; off >>= 1)
            sq += __shfl_down_sync(0xffffffffu, sq, off);
        if (lane == 0) atomicAdd(&rowsum[r], sq);   // 2 adds/row: order-invariant
        out0[(size_t)(row0 + r) * VDIM + v] = __fadd_rn(__fsub_rn(o, xv), xv);
    }
    __syncthreads();
    if (tid < BM) {
        float s = rowsum[tid];
        out1[row0 + tid] = s;
        out2[row0 + tid] = s;
    }

    // ---- last CTA computes entropy and resets state for the next replay ----
    __threadfence();                           // order this CTA's atomics/stores
    __shared__ int is_last;
    __syncthreads();
    if (tid == 0) {
        int d = atomicAdd(&g_done, 1);
        is_last = (d == GRID - 1);
    }
    __syncthreads();
    if (is_last) {
        // 128 threads x 8 bins each
        float term = 0.0f;
        #pragma unroll
        for (int t = 0; t < 8; t++) {
            int k = tid + t * THREADS;
            int c = g_counts[k];
            g_counts[k] = 0;
            if (c > 0) {
                float p = (float)c * (1.0f / 65536.0f);
                term -= p * logf(p);
            }
        }
        #pragma unroll
        for (int off = 16; off > 0; off >>= 1)
            term += __shfl_down_sync(0xffffffffu, term, off);
        float* wsum = rowsum;                  // reuse smem
        if (lane == 0) wsum[wrp] = term;
        __syncthreads();
        if (tid == 0) {
            float s = 0.0f;
            #pragma unroll
            for (int wI = 0; wI < 4; wI++) s += wsum[wI];
            *ent = s;
            g_done = 0;
        }
    }
}

// ---------------------------------------------------------------------------
extern "C" void kernel_launch(void* const* d_in, const int* in_sizes, int n_in,
                              void* d_out, int out_size) {
    const float* x;
    const float* emb;
    if (in_sizes[0] == NS_TOTAL * VDIM) {
        x   = (const float*)d_in[0];
        emb = (const float*)d_in[1];
    } else {
        x   = (const float*)d_in[1];
        emb = (const float*)d_in[0];
    }

    float* out0 = (float*)d_out;                        // 65536*64
    float* out1 = out0 + (size_t)NS_TOTAL * VDIM;       // 65536
    float* out2 = out1 + NS_TOTAL;                      // 65536
    float* ent  = out2 + NS_TOTAL;                      // 1

    cudaFuncSetAttribute(vq_main_kernel,
                         cudaFuncAttributeMaxDynamicSharedMemorySize, SMEM_BYTES);

    vq_prep_kernel<<<16, 256>>>(emb);
    vq_main_kernel<<<GRID, THREADS, SMEM_BYTES>>>(x, emb, out0, out1, out2, ent);
}

// round 14
// speedup vs baseline: 1.3883x; 1.0325x over previous
#include <cuda_runtime.h>
#include <math.h>

// Problem constants: N=8, S=8192, C=1, K=1024, V=64
#define NS_TOTAL 65536
#define VDIM 64
#define KCW 1024
#define BM 64                  // rows per CTA
#define BK 128
#define NCHUNK (KCW / BK)      // 8
#define GRID 1024
#define THREADS 256

#define XST 132                // x stride: 2*BM + 4 (16B-aligned rows)
#define EST 130                // e stride: BK + 2 (pad -> conflict-light, NO swizzle)
#define XS_FLOATS (VDIM * XST) // 8448
#define ES_FLOATS (VDIM * EST) // 8320
#define SMEM_BYTES ((XS_FLOATS + ES_FLOATS + KCW + BM) * 4)   // 71424 B -> 2 CTAs/SM w/ bounds

typedef unsigned long long ull;

__device__ float g_en[KCW];
__device__ int   g_counts[KCW];   // zero at load; last CTA re-zeroes each run
__device__ int   g_done;          // zero at load; last CTA resets each run

// Packed fp32x2 ops — IEEE rn per 32-bit lane. MUST keep register demand well
// under the launch-bounds cap or ptxas splits these to scalar FFMA (R12).
__device__ __forceinline__ ull ffma2(ull a, ull b, ull c) {
    ull d;
    asm("fma.rn.f32x2 %0, %1, %2, %3;" : "=l"(d) : "l"(a), "l"(b), "l"(c));
    return d;
}
__device__ __forceinline__ ull fmul2(ull a, ull b) {
    ull d;
    asm("mul.rn.f32x2 %0, %1, %2;" : "=l"(d) : "l"(a), "l"(b));
    return d;
}
__device__ __forceinline__ ull fadd2(ull a, ull b) {
    ull d;
    asm("add.rn.f32x2 %0, %1, %2;" : "=l"(d) : "l"(a), "l"(b));
    return d;
}
__device__ __forceinline__ void unpack2(ull v, float& lo, float& hi) {
    unsigned int l, h;
    asm("mov.b64 {%0, %1}, %2;" : "=r"(l), "=r"(h) : "l"(v));
    lo = __uint_as_float(l);
    hi = __uint_as_float(h);
}
__device__ __forceinline__ ull pack2(float lo, float hi) {
    ull v;
    asm("mov.b64 %0, {%1, %2};" : "=l"(v) : "f"(lo), "f"(hi));
    return v;
}

// ---------------------------------------------------------------------------
// Kernel 1: codeword norms via coalesced smem staging (bit-exact sequential).
// ---------------------------------------------------------------------------
__global__ void vq_prep_kernel(const float* __restrict__ emb) {
    __shared__ float se[64 * 65];
    const int tid = threadIdx.x;
    const int kb  = blockIdx.x * 64;
    const float4* e4 = reinterpret_cast<const float4*>(emb) + (size_t)kb * (VDIM / 4);
    #pragma unroll
    for (int t = 0; t < 4; t++) {
        int idx = tid + t * 256;           // 1024 float4
        int r   = idx >> 4;
        int v4  = idx & 15;
        float4 f = e4[idx];
        float* d = se + r * 65 + v4 * 4;
        d[0] = f.x; d[1] = f.y; d[2] = f.z; d[3] = f.w;
    }
    __syncthreads();
    if (tid < 64) {
        const float* er = se + tid * 65;
        float acc = 0.0f;
        #pragma unroll 8
        for (int v = 0; v < VDIM; v++)
            acc = __fadd_rn(acc, __fmul_rn(er[v], er[v]));
        g_en[kb + tid] = acc;
    }
}

// ---------------------------------------------------------------------------
// Kernel 2: fused GEMM + argmin + histogram + outputs + (last CTA) entropy
// grid 1024 (64 samples each), 256 threads, 2 CTAs/SM -> 16 warps/SM (4/SMSP)
// thread tile: 8 contiguous rows (warp-owned) x 4 codewords (2 packed pairs)
// ---------------------------------------------------------------------------
__global__ __launch_bounds__(THREADS, 2)
void vq_main_kernel(const float* __restrict__ x, const float* __restrict__ emb,
                    float* __restrict__ out0, float* __restrict__ out1,
                    float* __restrict__ out2, float* __restrict__ ent) {
    extern __shared__ float sm[];
    float* xs2  = sm;                          // [VDIM][XST] duplicated x pairs
    float* es   = sm + XS_FLOATS;              // [VDIM][EST] e chunk (transposed, padded)
    float* en_s = sm + XS_FLOATS + ES_FLOATS;  // [KCW] codeword norms
    float* xn_s = en_s + KCW;                  // [BM] row norms
    // post-loop overlays on es:
    int*   amin_s  = (int*)es;                 // [BM]
    float* rowsum  = es + BM;                  // [BM]

    const int tid  = threadIdx.x;
    const int lane = tid & 31;                 // 32 codeword-pair groups
    const int wrp  = tid >> 5;                 // 8 warps: rows 8*wrp .. 8*wrp+7
    const int row0 = blockIdx.x * BM;

    // ---- load x tile (coalesced float4), store duplicated pairs (v-major) ----
    const float4* x4 = reinterpret_cast<const float4*>(x) + (size_t)row0 * (VDIM / 4);
    #pragma unroll
    for (int t = 0; t < 4; t++) {
        int lin4 = tid + t * THREADS;          // 1024 float4
        int r    = lin4 >> 4;
        int v4   = lin4 & 15;
        float4 val = x4[lin4];
        *reinterpret_cast<float2*>(xs2 + (v4 * 4 + 0) * XST + 2 * r) = make_float2(val.x, val.x);
        *reinterpret_cast<float2*>(xs2 + (v4 * 4 + 1) * XST + 2 * r) = make_float2(val.y, val.y);
        *reinterpret_cast<float2*>(xs2 + (v4 * 4 + 2) * XST + 2 * r) = make_float2(val.z, val.z);
        *reinterpret_cast<float2*>(xs2 + (v4 * 4 + 3) * XST + 2 * r) = make_float2(val.w, val.w);
    }
    // ---- copy codeword norms into smem (4 per thread) ----
    #pragma unroll
    for (int t = 0; t < 4; t++) en_s[tid + t * THREADS] = g_en[tid + t * THREADS];
    __syncthreads();

    // ---- row norms ||x_r||^2 (sequential mul+add, v ascending) ----
    if (tid < BM) {
        float acc = 0.0f;
        const float* xr = xs2 + 2 * tid;
        #pragma unroll 8
        for (int v = 0; v < VDIM; v++) {
            float xv = xr[v * XST];
            acc = __fadd_rn(acc, __fmul_rn(xv, xv));
        }
        xn_s[tid] = acc;
    }

    float minv[8];
    int   mini[8];
    #pragma unroll
    for (int i = 0; i < 8; i++) { minv[i] = 3.402823466e38f; mini[i] = 0; }

    const ull NEG2 = 0xC0000000C0000000ULL;    // {-2.0f, -2.0f}

    // thread: rows r_i = 8*wrp + i (i<8), codewords k = c*128 + 64*m + 2*lane + {0,1} (m<2)
    for (int c = 0; c < NCHUNK; c++) {
        if (c > 0) __syncthreads();            // compute done before overwriting es
        const float4* e4 = reinterpret_cast<const float4*>(emb) + (size_t)c * (BK * VDIM / 4);
        #pragma unroll 2
        for (int t = 0; t < 8; t++) {
            int lin4 = tid + t * THREADS;      // 2048 float4
            int k    = lin4 >> 4;
            int v4   = lin4 & 15;
            float4 val = e4[lin4];
            es[(v4 * 4 + 0) * EST + k] = val.x;
            es[(v4 * 4 + 1) * EST + k] = val.y;
            es[(v4 * 4 + 2) * EST + k] = val.z;
            es[(v4 * 4 + 3) * EST + k] = val.w;
        }
        __syncthreads();

        ull acc[8][2];
        #pragma unroll
        for (int i = 0; i < 8; i++) { acc[i][0] = 0ULL; acc[i][1] = 0ULL; }

        const int txk = 2 * lane;
        // sequential FMA over v=0..63, single accumulator per (row, codeword)
        #pragma unroll 4
        for (int v = 0; v < VDIM; v++) {
            const float* ebase = es + v * EST + txk;
            ull ep0 = *reinterpret_cast<const ull*>(ebase);
            ull ep1 = *reinterpret_cast<const ull*>(ebase + 64);
            // x: 8 contiguous duplicated pairs, warp-uniform -> 4 broadcast LDS.128
            const ulonglong2* xvp =
                reinterpret_cast<const ulonglong2*>(xs2 + v * XST + wrp * 16);
            #pragma unroll
            for (int j = 0; j < 4; j++) {
                ulonglong2 q = xvp[j];
                acc[2 * j][0]     = ffma2(q.x, ep0, acc[2 * j][0]);
                acc[2 * j][1]     = ffma2(q.x, ep1, acc[2 * j][1]);
                acc[2 * j + 1][0] = ffma2(q.y, ep0, acc[2 * j + 1][0]);
                acc[2 * j + 1][1] = ffma2(q.y, ep1, acc[2 * j + 1][1]);
            }
        }

        // score = fl( fl( xn - fl(2*dot) ) + en ) via packed ops (exact per lane)
        #pragma unroll
        for (int m = 0; m < 2; m++) {
            int k0 = c * BK + 64 * m + txk;    // global codeword pair base
            ull en2 = *reinterpret_cast<const ull*>(en_s + k0);
            #pragma unroll
            for (int i = 0; i < 8; i++) {
                float xnv = xn_s[8 * wrp + i];
                ull s2 = fadd2(fadd2(pack2(xnv, xnv), fmul2(acc[i][m], NEG2)), en2);
                float s0, s1;
                unpack2(s2, s0, s1);
                if (s0 < minv[i]) { minv[i] = s0; mini[i] = k0; }
                if (s1 < minv[i]) { minv[i] = s1; mini[i] = k0 + 1; }
            }
        }
    }

    // ---- warp-local argmin reduction (all candidates for a row are in-warp) ----
    #pragma unroll
    for (int i = 0; i < 8; i++) {
        float bv = minv[i];
        int   bi = mini[i];
        #pragma unroll
        for (int off = 16; off > 0; off >>= 1) {
            float ov = __shfl_down_sync(0xffffffffu, bv, off);
            int   oi = __shfl_down_sync(0xffffffffu, bi, off);
            if (ov < bv || (ov == bv && oi < bi)) { bv = ov; bi = oi; }
        }
        mini[i] = bi;
    }
    __syncthreads();                           // all es reads done before overlay writes
    if (lane == 0) {
        #pragma unroll
        for (int i = 0; i < 8; i++) {
            int r = 8 * wrp + i;
            amin_s[r] = mini[i];
            rowsum[r] = 0.0f;
            atomicAdd(&g_counts[mini[i]], 1);
        }
    }
    __syncthreads();

    // ---- outputs: out0 = fl(fl(o - x) + x), out1 = out2 = sum_v (x-o)^2 ----
    #pragma unroll 4
    for (int t = 0; t < 16; t++) {
        int i = t * THREADS + tid;             // 4096 elements; warp = half a row
        int r = i >> 6;
        int v = i & 63;
        float o  = emb[amin_s[r] * VDIM + v];
        float xv = xs2[v * XST + 2 * r];
        float d  = __fsub_rn(xv, o);
        float sq = __fmul_rn(d, d);
        #pragma unroll
        for (int off = 16; off > 0; off >>= 1)
            sq += __shfl_down_sync(0xffffffffu, sq, off);
        if (lane == 0) atomicAdd(&rowsum[r], sq);   // 2 adds/row: order-invariant
        out0[(size_t)(row0 + r) * VDIM + v] = __fadd_rn(__fsub_rn(o, xv), xv);
    }
    __syncthreads();
    if (tid < BM) {
        float s = rowsum[tid];
        out1[row0 + tid] = s;
        out2[row0 + tid] = s;
    }

    // ---- last CTA computes entropy and resets state for the next replay ----
    __threadfence();                           // order this CTA's atomics/stores
    __shared__ int is_last;
    __syncthreads();
    if (tid == 0) {
        int d = atomicAdd(&g_done, 1);
        is_last = (d == GRID - 1);
    }
    __syncthreads();
    if (is_last) {
        // 256 threads x 4 bins each
        float term = 0.0f;
        #pragma unroll
        for (int t = 0; t < 4; t++) {
            int k = tid + t * THREADS;
            int c = g_counts[k];
            g_counts[k] = 0;
            if (c > 0) {
                float p = (float)c * (1.0f / 65536.0f);
                term -= p * logf(p);
            }
        }
        #pragma unroll
        for (int off = 16; off > 0; off >>= 1)
            term += __shfl_down_sync(0xffffffffu, term, off);
        float* wsum = rowsum;                  // reuse smem
        if (lane == 0) wsum[wrp] = term;
        __syncthreads();
        if (tid == 0) {
            float s = 0.0f;
            #pragma unroll
            for (int wI = 0; wI < 8; wI++) s += wsum[wI];
            *ent = s;
            g_done = 0;
        }
    }
}

// ---------------------------------------------------------------------------
extern "C" void kernel_launch(void* const* d_in, const int* in_sizes, int n_in,
                              void* d_out, int out_size) {
    const float* x;
    const float* emb;
    if (in_sizes[0] == NS_TOTAL * VDIM) {
        x   = (const float*)d_in[0];
        emb = (const float*)d_in[1];
    } else {
        x   = (const float*)d_in[1];
        emb = (const float*)d_in[0];
    }

    float* out0 = (float*)d_out;                        // 65536*64
    float* out1 = out0 + (size_t)NS_TOTAL * VDIM;       // 65536
    float* out2 = out1 + NS_TOTAL;                      // 65536
    float* ent  = out2 + NS_TOTAL;                      // 1

    cudaFuncSetAttribute(vq_main_kernel,
                         cudaFuncAttributeMaxDynamicSharedMemorySize, SMEM_BYTES);

    vq_prep_kernel<<<16, 256>>>(emb);
    vq_main_kernel<<<GRID, THREADS, SMEM_BYTES>>>(x, emb, out0, out1, out2, ent);
}

// round 15
// speedup vs baseline: 1.5301x; 1.1022x over previous
#include <cuda_runtime.h>
#include <math.h>

// Problem constants: N=8, S=8192, C=1, K=1024, V=64
#define NS_TOTAL 65536
#define VDIM 64
#define KCW 1024
#define BM 64                  // rows per CTA (16 per warp)
#define BK 128
#define NCHUNK (KCW / BK)      // 8
#define GRID 1024
#define THREADS 128

#define XST 132                // x stride: 2*BM + 4 (16B-aligned rows)
#define EST 130                // e stride: BK + 2 (padded, no swizzle)
#define XS_FLOATS (VDIM * XST) // 8448
#define ES_FLOATS (VDIM * EST) // 8320
#define SMEM_BYTES ((XS_FLOATS + ES_FLOATS + KCW + BM) * 4)   // 71424 B -> 3 CTAs/SM

typedef unsigned long long ull;

__device__ float g_en[KCW];
__device__ int   g_counts[KCW];   // zero at load; last CTA re-zeroes each run
__device__ int   g_done;          // zero at load; last CTA resets each run

// Packed fp32x2 ops — IEEE rn per 32-bit lane. Keep register demand well under
// the launch-bounds cap (168 here) or ptxas splits to scalar FFMA (R12 lesson).
__device__ __forceinline__ ull ffma2(ull a, ull b, ull c) {
    ull d;
    asm("fma.rn.f32x2 %0, %1, %2, %3;" : "=l"(d) : "l"(a), "l"(b), "l"(c));
    return d;
}
__device__ __forceinline__ ull fmul2(ull a, ull b) {
    ull d;
    asm("mul.rn.f32x2 %0, %1, %2;" : "=l"(d) : "l"(a), "l"(b));
    return d;
}
__device__ __forceinline__ ull fadd2(ull a, ull b) {
    ull d;
    asm("add.rn.f32x2 %0, %1, %2;" : "=l"(d) : "l"(a), "l"(b));
    return d;
}
__device__ __forceinline__ void unpack2(ull v, float& lo, float& hi) {
    unsigned int l, h;
    asm("mov.b64 {%0, %1}, %2;" : "=r"(l), "=r"(h) : "l"(v));
    lo = __uint_as_float(l);
    hi = __uint_as_float(h);
}
__device__ __forceinline__ ull pack2(float lo, float hi) {
    ull v;
    asm("mov.b64 %0, {%1, %2};" : "=l"(v) : "f"(lo), "f"(hi));
    return v;
}

// ---------------------------------------------------------------------------
// Kernel 1: codeword norms via coalesced smem staging (bit-exact sequential).
// ---------------------------------------------------------------------------
__global__ void vq_prep_kernel(const float* __restrict__ emb) {
    __shared__ float se[64 * 65];
    const int tid = threadIdx.x;
    const int kb  = blockIdx.x * 64;
    const float4* e4 = reinterpret_cast<const float4*>(emb) + (size_t)kb * (VDIM / 4);
    #pragma unroll
    for (int t = 0; t < 4; t++) {
        int idx = tid + t * 256;           // 1024 float4
        int r   = idx >> 4;
        int v4  = idx & 15;
        float4 f = e4[idx];
        float* d = se + r * 65 + v4 * 4;
        d[0] = f.x; d[1] = f.y; d[2] = f.z; d[3] = f.w;
    }
    __syncthreads();
    if (tid < 64) {
        const float* er = se + tid * 65;
        float acc = 0.0f;
        #pragma unroll 8
        for (int v = 0; v < VDIM; v++)
            acc = __fadd_rn(acc, __fmul_rn(er[v], er[v]));
        g_en[kb + tid] = acc;
    }
}

// ---------------------------------------------------------------------------
// Kernel 2: fused GEMM + argmin + histogram + outputs + (last CTA) entropy
// grid 1024 (64 samples each), 128 threads, 3 CTAs/SM (cap 168, ~130 used)
// thread tile: 16 contiguous rows (warp-owned) x 4 codewords (2 packed pairs)
// ---------------------------------------------------------------------------
__global__ __launch_bounds__(THREADS, 3)
void vq_main_kernel(const float* __restrict__ x, const float* __restrict__ emb,
                    float* __restrict__ out0, float* __restrict__ out1,
                    float* __restrict__ out2, float* __restrict__ ent) {
    extern __shared__ float sm[];
    float* xs2  = sm;                          // [VDIM][XST] duplicated x pairs
    float* es   = sm + XS_FLOATS;              // [VDIM][EST] e chunk (transposed, padded)
    float* en_s = sm + XS_FLOATS + ES_FLOATS;  // [KCW] codeword norms
    float* xn_s = en_s + KCW;                  // [BM] row norms
    // post-loop overlays on es:
    int*   amin_s  = (int*)es;                 // [BM]
    float* rowsum  = es + BM;                  // [BM]

    const int tid  = threadIdx.x;
    const int lane = tid & 31;                 // 32 codeword-pair groups
    const int wrp  = tid >> 5;                 // 4 warps: rows 16*wrp .. 16*wrp+15
    const int row0 = blockIdx.x * BM;

    // ---- load x tile (coalesced float4), store duplicated pairs (v-major) ----
    const float4* x4 = reinterpret_cast<const float4*>(x) + (size_t)row0 * (VDIM / 4);
    #pragma unroll
    for (int t = 0; t < 8; t++) {
        int lin4 = tid + t * THREADS;          // 1024 float4
        int r    = lin4 >> 4;
        int v4   = lin4 & 15;
        float4 val = x4[lin4];
        *reinterpret_cast<float2*>(xs2 + (v4 * 4 + 0) * XST + 2 * r) = make_float2(val.x, val.x);
        *reinterpret_cast<float2*>(xs2 + (v4 * 4 + 1) * XST + 2 * r) = make_float2(val.y, val.y);
        *reinterpret_cast<float2*>(xs2 + (v4 * 4 + 2) * XST + 2 * r) = make_float2(val.z, val.z);
        *reinterpret_cast<float2*>(xs2 + (v4 * 4 + 3) * XST + 2 * r) = make_float2(val.w, val.w);
    }
    // ---- copy codeword norms into smem (8 per thread) ----
    #pragma unroll
    for (int t = 0; t < 8; t++) en_s[tid + t * THREADS] = g_en[tid + t * THREADS];
    __syncthreads();

    // ---- row norms ||x_r||^2 (sequential mul+add, v ascending) ----
    if (tid < BM) {
        float acc = 0.0f;
        const float* xr = xs2 + 2 * tid;
        #pragma unroll 8
        for (int v = 0; v < VDIM; v++) {
            float xv = xr[v * XST];
            acc = __fadd_rn(acc, __fmul_rn(xv, xv));
        }
        xn_s[tid] = acc;
    }

    float minv[16];
    int   mini[16];
    #pragma unroll
    for (int i = 0; i < 16; i++) { minv[i] = 3.402823466e38f; mini[i] = 0; }

    const ull NEG2 = 0xC0000000C0000000ULL;    // {-2.0f, -2.0f}

    // thread: rows r_i = 16*wrp + i (i<16), codewords k = c*128 + 64*m + 2*lane + {0,1} (m<2)
    for (int c = 0; c < NCHUNK; c++) {
        if (c > 0) __syncthreads();            // compute done before overwriting es
        const float4* e4 = reinterpret_cast<const float4*>(emb) + (size_t)c * (BK * VDIM / 4);
        #pragma unroll 4
        for (int t = 0; t < 16; t++) {
            int lin4 = tid + t * THREADS;      // 2048 float4
            int k    = lin4 >> 4;
            int v4   = lin4 & 15;
            float4 val = e4[lin4];
            es[(v4 * 4 + 0) * EST + k] = val.x;
            es[(v4 * 4 + 1) * EST + k] = val.y;
            es[(v4 * 4 + 2) * EST + k] = val.z;
            es[(v4 * 4 + 3) * EST + k] = val.w;
        }
        __syncthreads();

        ull acc[16][2];
        #pragma unroll
        for (int i = 0; i < 16; i++) { acc[i][0] = 0ULL; acc[i][1] = 0ULL; }

        const int txk = 2 * lane;
        // sequential FMA over v=0..63, single accumulator per (row, codeword)
        #pragma unroll 2
        for (int v = 0; v < VDIM; v++) {
            const float* ebase = es + v * EST + txk;
            ull ep0 = *reinterpret_cast<const ull*>(ebase);
            ull ep1 = *reinterpret_cast<const ull*>(ebase + 64);
            // x: 16 contiguous duplicated pairs, warp-uniform broadcast LDS.128;
            // one xvp live at a time to bound register pressure
            const ulonglong2* xvp =
                reinterpret_cast<const ulonglong2*>(xs2 + v * XST + wrp * 32);
            #pragma unroll
            for (int j = 0; j < 8; j++) {
                ulonglong2 q = xvp[j];
                acc[2 * j][0]     = ffma2(q.x, ep0, acc[2 * j][0]);
                acc[2 * j][1]     = ffma2(q.x, ep1, acc[2 * j][1]);
                acc[2 * j + 1][0] = ffma2(q.y, ep0, acc[2 * j + 1][0]);
                acc[2 * j + 1][1] = ffma2(q.y, ep1, acc[2 * j + 1][1]);
            }
        }

        // score = fl( fl( xn - fl(2*dot) ) + en ) via packed ops (exact per lane)
        #pragma unroll
        for (int m = 0; m < 2; m++) {
            int k0 = c * BK + 64 * m + txk;    // global codeword pair base
            ull en2 = *reinterpret_cast<const ull*>(en_s + k0);
            #pragma unroll
            for (int i = 0; i < 16; i++) {
                float xnv = xn_s[16 * wrp + i];
                ull s2 = fadd2(fadd2(pack2(xnv, xnv), fmul2(acc[i][m], NEG2)), en2);
                float s0, s1;
                unpack2(s2, s0, s1);
                if (s0 < minv[i]) { minv[i] = s0; mini[i] = k0; }
                if (s1 < minv[i]) { minv[i] = s1; mini[i] = k0 + 1; }
            }
        }
    }

    // ---- warp-local argmin reduction (all candidates for a row are in-warp) ----
    #pragma unroll
    for (int i = 0; i < 16; i++) {
        float bv = minv[i];
        int   bi = mini[i];
        #pragma unroll
        for (int off = 16; off > 0; off >>= 1) {
            float ov = __shfl_down_sync(0xffffffffu, bv, off);
            int   oi = __shfl_down_sync(0xffffffffu, bi, off);
            if (ov < bv || (ov == bv && oi < bi)) { bv = ov; bi = oi; }
        }
        mini[i] = bi;
    }
    __syncthreads();                           // all es reads done before overlay writes
    if (lane == 0) {
        #pragma unroll
        for (int i = 0; i < 16; i++) {
            int r = 16 * wrp + i;
            amin_s[r] = mini[i];
            rowsum[r] = 0.0f;
            atomicAdd(&g_counts[mini[i]], 1);
        }
    }
    __syncthreads();

    // ---- outputs: out0 = fl(fl(o - x) + x), out1 = out2 = sum_v (x-o)^2 ----
    #pragma unroll 4
    for (int t = 0; t < 32; t++) {
        int i = t * THREADS + tid;             // 4096 elements; warp = half a row
        int r = i >> 6;
        int v = i & 63;
        float o  = emb[amin_s[r] * VDIM + v];
        float xv = xs2[v * XST + 2 * r];
        float d  = __fsub_rn(xv, o);
        float sq = __fmul_rn(d, d);
        #pragma unroll
        for (int off = 16; off > 0; off >>= 1)
            sq += __shfl_down_sync(0xffffffffu, sq, off);
        if (lane == 0) atomicAdd(&rowsum[r], sq);   // 2 adds/row: order-invariant
        out0[(size_t)(row0 + r) * VDIM + v] = __fadd_rn(__fsub_rn(o, xv), xv);
    }
    __syncthreads();
    if (tid < BM) {
        float s = rowsum[tid];
        out1[row0 + tid] = s;
        out2[row0 + tid] = s;
    }

    // ---- last CTA computes entropy and resets state for the next replay ----
    __threadfence();                           // order this CTA's atomics/stores
    __shared__ int is_last;
    __syncthreads();
    if (tid == 0) {
        int d = atomicAdd(&g_done, 1);
        is_last = (d == GRID - 1);
    }
    __syncthreads();
    if (is_last) {
        // 128 threads x 8 bins each
        float term = 0.0f;
        #pragma unroll
        for (int t = 0; t < 8; t++) {
            int k = tid + t * THREADS;
            int c = g_counts[k];
            g_counts[k] = 0;
            if (c > 0) {
                float p = (float)c * (1.0f / 65536.0f);
                term -= p * logf(p);
            }
        }
        #pragma unroll
        for (int off = 16; off > 0; off >>= 1)
            term += __shfl_down_sync(0xffffffffu, term, off);
        float* wsum = rowsum;                  // reuse smem
        if (lane == 0) wsum[wrp] = term;
        __syncthreads();
        if (tid == 0) {
            float s = 0.0f;
            #pragma unroll
            for (int wI = 0; wI < 4; wI++) s += wsum[wI];
            *ent = s;
            g_done = 0;
        }
    }
}

// ---------------------------------------------------------------------------
extern "C" void kernel_launch(void* const* d_in, const int* in_sizes, int n_in,
                              void* d_out, int out_size) {
    const float* x;
    const float* emb;
    if (in_sizes[0] == NS_TOTAL * VDIM) {
        x   = (const float*)d_in[0];
        emb = (const float*)d_in[1];
    } else {
        x   = (const float*)d_in[1];
        emb = (const float*)d_in[0];
    }

    float* out0 = (float*)d_out;                        // 65536*64
    float* out1 = out0 + (size_t)NS_TOTAL * VDIM;       // 65536
    float* out2 = out1 + NS_TOTAL;                      // 65536
    float* ent  = out2 + NS_TOTAL;                      // 1

    cudaFuncSetAttribute(vq_main_kernel,
                         cudaFuncAttributeMaxDynamicSharedMemorySize, SMEM_BYTES);

    vq_prep_kernel<<<16, 256>>>(emb);
    vq_main_kernel<<<GRID, THREADS, SMEM_BYTES>>>(x, emb, out0, out1, out2, ent);
}